// round 8
// baseline (speedup 1.0000x reference)
#include <cuda_runtime.h>
#include <cuda_bf16.h>

// Problem constants (fixed by reference_code)
#define HH 768
#define WW 768
#define BB 9
#define CC 3
#define NS 100          // N_SAMPLES
#define MM 13           // offsets with dy^2+dx^2 <= 4
#define DD 27           // PATCH*PATCH*C
#define DP 28           // padded stride: 28 floats = 7 float4, rows 16B-aligned
#define NPATCH (BB * MM)            // 117
#define NTHREADS 256                // 8 warps
// scale = (1/T^2) / (K * B * NS) = 4 / (8*9*100); divide by counts[n] per block
#define BASE_SCALE (4.0f / (8.0f * 9.0f * 100.0f))

// Fixed-point accumulation: partial * 2^44 rounded to integer. Integer adds
// commute -> bit-deterministic total regardless of block arrival order.
#define FIX_SCALE   1.7592186044416e13f      // 2^44
#define FIX_INV     5.684341886080802e-14    // 2^-44 (double)

// Nibble-packed offsets (value+2 in 4 bits at position 4*m), pure-ALU decode:
// offy: -2,-1,-1,-1, 0, 0, 0, 0, 0, 1, 1, 1, 2
// offx:  0,-1, 0, 1,-2,-1, 0, 1, 2,-1, 0, 1, 0
#define OY_PACK 0x4333222221110ULL
#define OX_PACK 0x2321432103212ULL
#define OFFY(m) ((int)((OY_PACK >> (4 * (m))) & 15ULL) - 2)
#define OFFX(m) ((int)((OX_PACK >> (4 * (m))) & 15ULL) - 2)

__device__ unsigned long long g_sum  = 0ULL;  // fixed-point loss accumulator
__device__ unsigned int       g_done = 0;     // completion counter

__global__ __launch_bounds__(NTHREADS)
void fused_kernel(const float* __restrict__ latents,
                  const int*   __restrict__ anchor_idx,
                  float*       __restrict__ out) {
    __shared__ __align__(16) float sh[NPATCH * DP];  // 117 NORMALIZED patch vectors
    __shared__ int   s_valid[MM];
    __shared__ float s_wsum[NTHREADS / 32];

    const int tid  = threadIdx.x;
    const int n    = blockIdx.x;
    const int a    = __ldg(&anchor_idx[n]);
    const int ay   = a / WW;
    const int ax   = a - ay * WW;

    if (tid < MM) {
        const int ny = ay + OFFY(tid);
        const int nx = ax + OFFX(tid);
        s_valid[tid] = (ny >= 0 && ny < HH && nx >= 0 && nx < WW) ? 1 : 0;
    }

    // --- Phase 1: one thread per patch. 27 scattered LDG (independent, MLP=27),
    //     normalize in registers, store as 7 conflict-free STS.128 (pad word = 0).
    if (tid < NPATCH) {
        const int j = tid / MM;
        const int m = tid - j * MM;
        int py = ay + OFFY(m);
        int px = ax + OFFX(m);
        py = min(max(py, 0), HH - 1);        // matches jnp.clip on neighbor pos
        px = min(max(px, 0), WW - 1);

        const float* base = latents + (size_t)j * (HH * WW * CC);
        float v[DD];
        float ss = 0.0f;
        #pragma unroll
        for (int ky = -1; ky <= 1; ky++) {
            const int yy = min(max(py + ky, 0), HH - 1);     // edge-pad clamp
            #pragma unroll
            for (int kx = -1; kx <= 1; kx++) {
                const int xx = min(max(px + kx, 0), WW - 1);
                const float* p = base + ((size_t)yy * WW + xx) * CC;
                #pragma unroll
                for (int c = 0; c < CC; c++) {
                    const float f = __ldg(p + c);
                    v[((ky + 1) * 3 + (kx + 1)) * 3 + c] = f;
                    ss += f * f;
                }
            }
        }
        const float inv = 1.0f / fmaxf(sqrtf(ss), 1e-12f);
        float4* dst = (float4*)&sh[tid * DP];
        #pragma unroll
        for (int q = 0; q < 6; q++)
            dst[q] = make_float4(v[4*q]*inv, v[4*q+1]*inv, v[4*q+2]*inv, v[4*q+3]*inv);
        dst[6] = make_float4(v[24]*inv, v[25]*inv, v[26]*inv, 0.0f);
    }
    __syncthreads();

    // --- Phase 2: lane = one neighbor vector cached in registers (7x LDS.128,
    //     conflict-free). Anchors stream in as broadcast LDS.128 (uniform
    //     address). Warps 0-3 cover b=0..3; warps 4-7 cover b=4..8.
    const int w     = tid >> 5;
    const int lane  = tid & 31;
    const int chunk = w & 3;                 // 4 chunks x 32 lanes >= 117
    const int p     = chunk * 32 + lane;     // neighbor (j,m) index
    const bool have = (p < NPATCH);
    const int pp    = have ? p : 0;
    const int j     = pp / MM;
    const int m     = pp - j * MM;
    const bool ok   = have && (s_valid[m] != 0);

    float4 v4[7];
    {
        const float4* vr = (const float4*)&sh[pp * DP];
        #pragma unroll
        for (int q = 0; q < 7; q++) v4[q] = vr[q];
    }

    const int b0 = (w < 4) ? 0 : 4;
    const int b1 = (w < 4) ? 4 : 9;
    float acc = 0.0f;
    for (int b = b0; b < b1; b++) {
        const float4* ar = (const float4*)&sh[(b * MM + 6) * DP]; // anchor = offset (0,0)
        float d0 = 0.0f, d1 = 0.0f, d2 = 0.0f, d3 = 0.0f;
        #pragma unroll
        for (int q = 0; q < 7; q++) {
            const float4 a4 = ar[q];         // broadcast: uniform address in warp
            d0 = fmaf(a4.x, v4[q].x, d0);
            d1 = fmaf(a4.y, v4[q].y, d1);
            d2 = fmaf(a4.z, v4[q].z, d2);
            d3 = fmaf(a4.w, v4[q].w, d3);    // pad lane: 0*0
        }
        const float d = (d0 + d1) + (d2 + d3);
        if (ok && j != b) acc += d * d;
    }

    // --- Block reduction (deterministic tree over 8 warps) ---
    #pragma unroll
    for (int o = 16; o > 0; o >>= 1)
        acc += __shfl_down_sync(0xFFFFFFFFu, acc, o);
    if (lane == 0) s_wsum[w] = acc;
    __syncthreads();

    // --- Tail: fixed-point atomic accumulation (deterministic), then a
    //     release-increment on the counter; last block converts and resets.
    if (w == 0) {
        unsigned int prev = 0;
        if (lane == 0) {
            float s = 0.0f;
            #pragma unroll
            for (int k = 0; k < NTHREADS / 32; k++) s += s_wsum[k];
            int cnt = 0;
            #pragma unroll
            for (int mm = 0; mm < MM; mm++) cnt += s_valid[mm];
            const float partial = s * (BASE_SCALE / (float)cnt);  // >= 0
            const long long q = __float2ll_rn(partial * FIX_SCALE);
            atomicAdd(&g_sum, (unsigned long long)q);
            // acq_rel: release publishes the g_sum add; acquire on the final
            // increment makes every prior add visible to this thread.
            asm volatile("atom.acq_rel.gpu.add.u32 %0, [%1], %2;"
                         : "=r"(prev) : "l"(&g_done), "r"(1u) : "memory");
            if (prev == NS - 1) {
                const unsigned long long total =
                    *(volatile unsigned long long*)&g_sum;
                out[0] = (float)((double)total * FIX_INV);
                g_sum  = 0ULL;               // reset for next graph replay
                g_done = 0;
            }
        }
    }
}

extern "C" void kernel_launch(void* const* d_in, const int* in_sizes, int n_in,
                              void* d_out, int out_size) {
    const float* latents    = (const float*)d_in[0];
    const int*   anchor_idx = (const int*)d_in[1];
    float*       out        = (float*)d_out;

    fused_kernel<<<NS, NTHREADS>>>(latents, anchor_idx, out);
}